// round 1
// baseline (speedup 1.0000x reference)
#include <cuda_runtime.h>

#define TOKENS 4096
#define DM 1024
#define DF 4096
#define NE 8

// ---- device scratch (static; no runtime allocation) ----
__device__ int   g_cnt[NE];
__device__ int   g_tok[NE][TOKENS];
__device__ int   g_slot[NE][TOKENS];
__device__ float g_h[(size_t)NE * TOKENS * DF];     // 512 MB intermediate h per expert
__device__ float g_buf[(size_t)2 * TOKENS * DM];    // per-slot staged outputs (32 MB)

// ---------------------------------------------------------------------------
// 0) zero routing counters
// ---------------------------------------------------------------------------
__global__ void zero_cnt_kernel() {
    if (threadIdx.x < NE) g_cnt[threadIdx.x] = 0;
}

// ---------------------------------------------------------------------------
// 1) routing: one warp per token. logits = x @ Wg + bg ; top-2 (softmax is
//    monotonic, so argtop on logits == argtop on softmax). Ties -> lower index
//    first, matching jax.lax.top_k stable behavior.
// ---------------------------------------------------------------------------
__global__ void route_kernel(const float* __restrict__ x,
                             const float* __restrict__ Wg,
                             const float* __restrict__ bg) {
    int warp  = threadIdx.x >> 5;
    int lane  = threadIdx.x & 31;
    int token = blockIdx.x * 8 + warp;
    if (token >= TOKENS) return;

    float acc[NE];
#pragma unroll
    for (int e = 0; e < NE; e++) acc[e] = 0.f;

    const float* xrow = x + (size_t)token * DM;
    for (int k = lane; k < DM; k += 32) {
        float xv = xrow[k];
        const float* wr = Wg + (size_t)k * NE;
#pragma unroll
        for (int e = 0; e < NE; e++) acc[e] += xv * wr[e];
    }
#pragma unroll
    for (int e = 0; e < NE; e++) {
#pragma unroll
        for (int o = 16; o > 0; o >>= 1)
            acc[e] += __shfl_xor_sync(0xffffffffu, acc[e], o);
    }
    if (lane == 0) {
        float lg[NE];
#pragma unroll
        for (int e = 0; e < NE; e++) lg[e] = acc[e] + bg[e];
        int e0 = 0;
#pragma unroll
        for (int e = 1; e < NE; e++) if (lg[e] > lg[e0]) e0 = e;
        int e1 = (e0 == 0) ? 1 : 0;
#pragma unroll
        for (int e = 0; e < NE; e++) if (e != e0 && lg[e] > lg[e1]) e1 = e;

        int p0 = atomicAdd(&g_cnt[e0], 1);
        g_tok[e0][p0]  = token;
        g_slot[e0][p0] = 0;
        int p1 = atomicAdd(&g_cnt[e1], 1);
        g_tok[e1][p1]  = token;
        g_slot[e1][p1] = 1;
    }
}

// ---------------------------------------------------------------------------
// 2/3) grouped SGEMM: BM=BN=128, BK=8, 256 threads, 8x8 microtile per thread.
//  GATHER_A: A rows gathered from x via g_tok[e]  (GEMM1)
//            else A = g_h[e] rows 0..cnt          (GEMM2)
//  RELU    : apply relu after bias                (GEMM1)
//  SCATTER : write to g_buf[slot][token]          (GEMM2), else g_h[e][row]
// ---------------------------------------------------------------------------
template <int KDIM, int NDIM, bool GATHER_A, bool RELU, bool SCATTER_C>
__global__ void __launch_bounds__(256, 2)
gemm_kernel(const float* __restrict__ Aext,     // x (GEMM1) / unused (GEMM2)
            const float* __restrict__ Bbase,    // W1 / W2, per-expert stride KDIM*NDIM
            const float* __restrict__ bias)     // b1 / b2, per-expert stride NDIM
{
    int e   = blockIdx.z;
    int cnt = g_cnt[e];
    int m0  = blockIdx.y * 128;
    if (m0 >= cnt) return;
    int n0  = blockIdx.x * 128;

    __shared__ float As[8][128];
    __shared__ float Bs[8][128];

    int t  = threadIdx.x;
    // A tile loader: thread -> (row, k-quad)
    int ar   = t >> 1;            // 0..127
    int ak   = (t & 1) * 4;       // 0 or 4
    int amr  = m0 + ar;
    int amrc = min(amr, cnt - 1); // clamp padded rows to a valid row (stores masked)
    const float* Arow;
    if (GATHER_A) Arow = Aext + (size_t)g_tok[e][amrc] * KDIM;
    else          Arow = g_h + ((size_t)e * TOKENS + amrc) * KDIM;

    // B tile loader: thread -> (k row, n-quad)
    int bk = t >> 5;              // 0..7
    int bn = (t & 31) * 4;        // 0..124
    const float* Bptr = Bbase + (size_t)e * KDIM * NDIM + (size_t)bk * NDIM + n0 + bn;

    int tx = t & 15, ty = t >> 4;

    float acc[8][8];
#pragma unroll
    for (int i = 0; i < 8; i++)
#pragma unroll
        for (int j = 0; j < 8; j++) acc[i][j] = 0.f;

    for (int k0 = 0; k0 < KDIM; k0 += 8) {
        float4 av = *(const float4*)(Arow + k0 + ak);
        float4 bv = *(const float4*)(Bptr + (size_t)k0 * NDIM);
        __syncthreads();
        As[ak + 0][ar] = av.x;
        As[ak + 1][ar] = av.y;
        As[ak + 2][ar] = av.z;
        As[ak + 3][ar] = av.w;
        *(float4*)&Bs[bk][bn] = bv;
        __syncthreads();
#pragma unroll
        for (int k = 0; k < 8; k++) {
            float4 a0 = *(const float4*)&As[k][ty * 8];
            float4 a1 = *(const float4*)&As[k][ty * 8 + 4];
            float4 b0 = *(const float4*)&Bs[k][tx * 8];
            float4 b1 = *(const float4*)&Bs[k][tx * 8 + 4];
            float a[8] = {a0.x, a0.y, a0.z, a0.w, a1.x, a1.y, a1.z, a1.w};
            float b[8] = {b0.x, b0.y, b0.z, b0.w, b1.x, b1.y, b1.z, b1.w};
#pragma unroll
            for (int i = 0; i < 8; i++)
#pragma unroll
                for (int j = 0; j < 8; j++) acc[i][j] += a[i] * b[j];
        }
    }

    // epilogue
    float bvj[8];
#pragma unroll
    for (int j = 0; j < 8; j++)
        bvj[j] = bias[(size_t)e * NDIM + n0 + tx * 8 + j];

#pragma unroll
    for (int i = 0; i < 8; i++) {
        int gr = m0 + ty * 8 + i;
        if (gr < cnt) {
            float o[8];
#pragma unroll
            for (int j = 0; j < 8; j++) {
                float v = acc[i][j] + bvj[j];
                if (RELU) v = fmaxf(v, 0.f);
                o[j] = v;
            }
            float* dst;
            if (SCATTER_C) {
                int token = g_tok[e][gr];
                int slot  = g_slot[e][gr];
                dst = g_buf + ((size_t)slot * TOKENS + token) * NDIM + n0 + tx * 8;
            } else {
                dst = g_h + ((size_t)e * TOKENS + gr) * NDIM + n0 + tx * 8;
            }
            *(float4*)dst       = make_float4(o[0], o[1], o[2], o[3]);
            *(float4*)(dst + 4) = make_float4(o[4], o[5], o[6], o[7]);
        }
    }
}

// ---------------------------------------------------------------------------
// 4) combine: out = buf[slot0] + buf[slot1]. Every (slot, token) row is
//    written each launch (each token has exactly 2 distinct experts), so no
//    zero-init needed anywhere.
// ---------------------------------------------------------------------------
__global__ void combine_kernel(float* __restrict__ out) {
    int i = blockIdx.x * blockDim.x + threadIdx.x;   // float4 index
    const float4* b0 = (const float4*)g_buf;
    const float4* b1 = (const float4*)(g_buf + (size_t)TOKENS * DM);
    float4 u = b0[i], v = b1[i];
    ((float4*)out)[i] = make_float4(u.x + v.x, u.y + v.y, u.z + v.z, u.w + v.w);
}

// ---------------------------------------------------------------------------
extern "C" void kernel_launch(void* const* d_in, const int* in_sizes, int n_in,
                              void* d_out, int out_size) {
    const float* x  = (const float*)d_in[0];
    const float* Wg = (const float*)d_in[1];
    const float* bg = (const float*)d_in[2];
    const float* W1 = (const float*)d_in[3];
    const float* b1 = (const float*)d_in[4];
    const float* W2 = (const float*)d_in[5];
    const float* b2 = (const float*)d_in[6];
    float* out = (float*)d_out;

    zero_cnt_kernel<<<1, 32>>>();
    route_kernel<<<TOKENS / 8, 256>>>(x, Wg, bg);

    // GEMM1: h = relu(gather(x) @ W1[e] + b1[e])  -> g_h
    gemm_kernel<DM, DF, true, true, false>
        <<<dim3(DF / 128, TOKENS / 128, NE), 256>>>(x, W1, b1);

    // GEMM2: y = h @ W2[e] + b2[e]  -> scatter to g_buf[slot][token]
    gemm_kernel<DF, DM, false, false, true>
        <<<dim3(DM / 128, TOKENS / 128, NE), 256>>>(nullptr, W2, b2);

    combine_kernel<<<(TOKENS * DM / 4) / 256, 256>>>(out);
}

// round 3
// speedup vs baseline: 2.0742x; 2.0742x over previous
#include <cuda_runtime.h>
#include <cuda_bf16.h>
#include <cstdint>

#define TOKENS 4096
#define DM 1024
#define DF 4096
#define NE 8

typedef __nv_bfloat16 bf16;

// ---------------- device scratch (static, no runtime alloc) ----------------
__device__ int g_cnt[NE];
__device__ int g_tok[NE][TOKENS];
__device__ int g_slot[NE][TOKENS];
__device__ __align__(16) bf16 g_xh[(size_t)TOKENS * DM];
__device__ __align__(16) bf16 g_xl[(size_t)TOKENS * DM];
__device__ __align__(16) bf16 g_w1h[(size_t)NE * DF * DM];   // [E][N=DF][K=DM]
__device__ __align__(16) bf16 g_w1l[(size_t)NE * DF * DM];
__device__ __align__(16) bf16 g_w2h[(size_t)NE * DM * DF];   // [E][N=DM][K=DF]
__device__ __align__(16) bf16 g_w2l[(size_t)NE * DM * DF];
__device__ __align__(16) bf16 g_hh[(size_t)NE * TOKENS * DF];
__device__ __align__(16) bf16 g_hl[(size_t)NE * TOKENS * DF];
__device__ __align__(16) float g_buf[(size_t)2 * TOKENS * DM];

// ---------------- helpers ----------------
__device__ __forceinline__ uint32_t smem_u32(const void* p) {
    uint32_t a;
    asm("{ .reg .u64 t; cvta.to.shared.u64 t, %1; cvt.u32.u64 %0, t; }" : "=r"(a) : "l"(p));
    return a;
}
__device__ __forceinline__ void cp16(uint32_t s, const void* g) {
    asm volatile("cp.async.cg.shared.global [%0], [%1], 16;" :: "r"(s), "l"(g) : "memory");
}
__device__ __forceinline__ void cp_commit() {
    asm volatile("cp.async.commit_group;" ::: "memory");
}
__device__ __forceinline__ void cp_wait0() {
    asm volatile("cp.async.wait_group 0;" ::: "memory");
}
#define MMA_BF16(acc, a, b)                                                      \
    asm volatile(                                                                \
        "mma.sync.aligned.m16n8k16.row.col.f32.bf16.bf16.f32 "                   \
        "{%0,%1,%2,%3},{%4,%5,%6,%7},{%8,%9},{%0,%1,%2,%3};"                     \
        : "+f"((acc)[0]), "+f"((acc)[1]), "+f"((acc)[2]), "+f"((acc)[3])         \
        : "r"((a)[0]), "r"((a)[1]), "r"((a)[2]), "r"((a)[3]),                    \
          "r"((b)[0]), "r"((b)[1]))

__device__ __forceinline__ void split2(float a, float b, __nv_bfloat162& h, __nv_bfloat162& l) {
    bf16 ha = __float2bfloat16_rn(a);
    bf16 hb = __float2bfloat16_rn(b);
    h.x = ha; h.y = hb;
    l.x = __float2bfloat16_rn(a - __bfloat162float(ha));
    l.y = __float2bfloat16_rn(b - __bfloat162float(hb));
}

// ---------------- 0) zero counters ----------------
__global__ void zero_cnt_kernel() {
    if (threadIdx.x < NE) g_cnt[threadIdx.x] = 0;
}

// ---------------- 1) routing ----------------
__global__ void route_kernel(const float* __restrict__ x,
                             const float* __restrict__ Wg,
                             const float* __restrict__ bg) {
    int warp = threadIdx.x >> 5;
    int lane = threadIdx.x & 31;
    int token = blockIdx.x * 8 + warp;
    if (token >= TOKENS) return;

    float acc[NE];
#pragma unroll
    for (int e = 0; e < NE; e++) acc[e] = 0.f;
    const float* xrow = x + (size_t)token * DM;
    for (int k = lane; k < DM; k += 32) {
        float xv = xrow[k];
        const float* wr = Wg + (size_t)k * NE;
#pragma unroll
        for (int e = 0; e < NE; e++) acc[e] += xv * wr[e];
    }
#pragma unroll
    for (int e = 0; e < NE; e++)
#pragma unroll
        for (int o = 16; o > 0; o >>= 1)
            acc[e] += __shfl_xor_sync(0xffffffffu, acc[e], o);
    if (lane == 0) {
        float lg[NE];
#pragma unroll
        for (int e = 0; e < NE; e++) lg[e] = acc[e] + bg[e];
        int e0 = 0;
#pragma unroll
        for (int e = 1; e < NE; e++) if (lg[e] > lg[e0]) e0 = e;
        int e1 = (e0 == 0) ? 1 : 0;
#pragma unroll
        for (int e = 0; e < NE; e++) if (e != e0 && lg[e] > lg[e1]) e1 = e;
        int p0 = atomicAdd(&g_cnt[e0], 1);
        g_tok[e0][p0] = token; g_slot[e0][p0] = 0;
        int p1 = atomicAdd(&g_cnt[e1], 1);
        g_tok[e1][p1] = token; g_slot[e1][p1] = 1;
    }
}

// ---------------- 2) fp32 -> bf16 hi/lo converts ----------------
__global__ void convert_x_kernel(const float* __restrict__ x) {
    int i = blockIdx.x * blockDim.x + threadIdx.x;   // float4 index
    float4 v = ((const float4*)x)[i];
    __nv_bfloat162 h0, l0, h1, l1;
    split2(v.x, v.y, h0, l0);
    split2(v.z, v.w, h1, l1);
    ((__nv_bfloat162*)g_xh)[2 * i]     = h0;
    ((__nv_bfloat162*)g_xh)[2 * i + 1] = h1;
    ((__nv_bfloat162*)g_xl)[2 * i]     = l0;
    ((__nv_bfloat162*)g_xl)[2 * i + 1] = l1;
}

// transpose + split: W [E][K][N] fp32 -> [E][N][K] bf16 hi/lo
template <int K, int N, bool W1SEL>
__global__ void convert_w_kernel(const float* __restrict__ W) {
    __shared__ float t[32][33];
    bf16* Oh = W1SEL ? g_w1h : g_w2h;
    bf16* Ol = W1SEL ? g_w1l : g_w2l;
    int e = blockIdx.z;
    int n0 = blockIdx.x * 32, k0 = blockIdx.y * 32;
    int tx = threadIdx.x, ty = threadIdx.y;  // 32 x 8
    const float* Wp = W + (size_t)e * K * N;
#pragma unroll
    for (int i = 0; i < 4; i++)
        t[ty + 8 * i][tx] = Wp[(size_t)(k0 + ty + 8 * i) * N + n0 + tx];
    __syncthreads();
    bf16* oh = Oh + (size_t)e * N * K;
    bf16* ol = Ol + (size_t)e * N * K;
#pragma unroll
    for (int i = 0; i < 4; i++) {
        float v = t[tx][ty + 8 * i];
        bf16 h = __float2bfloat16_rn(v);
        bf16 l = __float2bfloat16_rn(v - __bfloat162float(h));
        size_t o = (size_t)(n0 + ty + 8 * i) * K + k0 + tx;
        oh[o] = h; ol[o] = l;
    }
}

// ---------------- 3) split-bf16 HMMA grouped GEMM ----------------
// BM=128, BN=128, BK=32. 256 threads = 8 warps (2 M x 4 N), warp tile 64x32.
// SMEM stage: Ah | Al | Bh | Bl, each 128 rows x 40 bf16 (80B padded rows).
#define ROWB   80
#define TILEB  (128 * ROWB)          // 10240 B
#define STAGEB (4 * TILEB)           // 40960 B
#define SMEMB  (2 * STAGEB + 512)

template <int KDIM>
__device__ __forceinline__ void stage_load(uint32_t sb, int k0,
                                           const bf16* __restrict__ Ah, const bf16* __restrict__ Al,
                                           const bf16* __restrict__ Bh, const bf16* __restrict__ Bl,
                                           const int* __restrict__ srow, int n0, int tid) {
#pragma unroll
    for (int half = 0; half < 2; half++) {
        int c = tid + half * 256;        // 0..511
        int r = c >> 2, j = c & 3;
        uint32_t so = (uint32_t)(r * ROWB + j * 16);
        size_t ga = (size_t)srow[r] * KDIM + k0 + j * 8;
        size_t gb = (size_t)(n0 + r) * KDIM + k0 + j * 8;
        cp16(sb + so,             Ah + ga);
        cp16(sb + TILEB + so,     Al + ga);
        cp16(sb + 2 * TILEB + so, Bh + gb);
        cp16(sb + 3 * TILEB + so, Bl + gb);
    }
}

template <int KDIM, int NDIM, bool G1>
__global__ void __launch_bounds__(256, 1)
moe_gemm(const float* __restrict__ bias) {
    const int e = blockIdx.z;
    const int cnt = g_cnt[e];
    const int m0 = blockIdx.y * 128;
    if (m0 >= cnt) return;
    const int n0 = blockIdx.x * 128;
    constexpr int NT = KDIM / 32;

    extern __shared__ char smem[];
    const uint32_t sb = smem_u32(smem);
    const int tid = threadIdx.x, wid = tid >> 5, lane = tid & 31;
    const int warp_m = wid >> 2, warp_n = wid & 3;
    const int g = lane >> 2, tg = lane & 3;
    int* srow = (int*)(smem + 2 * STAGEB);

    if (tid < 128) {
        int rr = min(m0 + tid, cnt - 1);
        srow[tid] = G1 ? g_tok[e][rr] : (e * TOKENS + rr);
    }
    __syncthreads();

    const bf16* Ah = G1 ? g_xh : g_hh;
    const bf16* Al = G1 ? g_xl : g_hl;
    const bf16* Bh = (G1 ? g_w1h : g_w2h) + (size_t)e * NDIM * KDIM;
    const bf16* Bl = (G1 ? g_w1l : g_w2l) + (size_t)e * NDIM * KDIM;

    float acc[4][4][4];
#pragma unroll
    for (int i = 0; i < 4; i++)
#pragma unroll
        for (int j = 0; j < 4; j++)
#pragma unroll
            for (int k = 0; k < 4; k++) acc[i][j][k] = 0.f;

    stage_load<KDIM>(sb, 0, Ah, Al, Bh, Bl, srow, n0, tid);
    cp_commit();

    const int aRowBase = warp_m * 64 + g;
    const int bRowBase = warp_n * 32 + g;

    for (int it = 0; it < NT; it++) {
        cp_wait0();
        __syncthreads();
        if (it + 1 < NT) {
            stage_load<KDIM>(sb + ((it + 1) & 1) * STAGEB, (it + 1) * 32,
                             Ah, Al, Bh, Bl, srow, n0, tid);
            cp_commit();
        }
        const char* st = smem + (it & 1) * STAGEB;
#pragma unroll
        for (int ks = 0; ks < 2; ks++) {
            const int colb = (ks * 16 + tg * 2) * 2;   // byte offset within row
            uint32_t ah[4][4], al[4][4], bh[4][2], bl[4][2];
#pragma unroll
            for (int mf = 0; mf < 4; mf++) {
                int ro = (aRowBase + mf * 16) * ROWB + colb;
                ah[mf][0] = *(const uint32_t*)(st + ro);
                ah[mf][1] = *(const uint32_t*)(st + ro + 8 * ROWB);
                ah[mf][2] = *(const uint32_t*)(st + ro + 16);
                ah[mf][3] = *(const uint32_t*)(st + ro + 8 * ROWB + 16);
                al[mf][0] = *(const uint32_t*)(st + TILEB + ro);
                al[mf][1] = *(const uint32_t*)(st + TILEB + ro + 8 * ROWB);
                al[mf][2] = *(const uint32_t*)(st + TILEB + ro + 16);
                al[mf][3] = *(const uint32_t*)(st + TILEB + ro + 8 * ROWB + 16);
            }
#pragma unroll
            for (int nf = 0; nf < 4; nf++) {
                int ro = (bRowBase + nf * 8) * ROWB + colb;
                bh[nf][0] = *(const uint32_t*)(st + 2 * TILEB + ro);
                bh[nf][1] = *(const uint32_t*)(st + 2 * TILEB + ro + 16);
                bl[nf][0] = *(const uint32_t*)(st + 3 * TILEB + ro);
                bl[nf][1] = *(const uint32_t*)(st + 3 * TILEB + ro + 16);
            }
#pragma unroll
            for (int mf = 0; mf < 4; mf++)
#pragma unroll
                for (int nf = 0; nf < 4; nf++) {
                    MMA_BF16(acc[mf][nf], ah[mf], bh[nf]);
                    MMA_BF16(acc[mf][nf], ah[mf], bl[nf]);
                    MMA_BF16(acc[mf][nf], al[mf], bh[nf]);
                }
        }
        __syncthreads();
    }

    // ---------------- epilogue ----------------
#pragma unroll
    for (int mf = 0; mf < 4; mf++) {
        int r0 = m0 + warp_m * 64 + mf * 16 + g;
        int r1 = r0 + 8;
#pragma unroll
        for (int nf = 0; nf < 4; nf++) {
            int col = n0 + warp_n * 32 + nf * 8 + tg * 2;
            float bv0 = bias[e * NDIM + col];
            float bv1 = bias[e * NDIM + col + 1];
#pragma unroll
            for (int h = 0; h < 2; h++) {
                int r = h ? r1 : r0;
                if (r >= cnt) continue;
                float v0 = acc[mf][nf][2 * h]     + bv0;
                float v1 = acc[mf][nf][2 * h + 1] + bv1;
                if (G1) {
                    v0 = fmaxf(v0, 0.f);
                    v1 = fmaxf(v1, 0.f);
                    __nv_bfloat162 hh, ll;
                    split2(v0, v1, hh, ll);
                    size_t o = ((size_t)(e * TOKENS + r)) * DF + col;
                    *(__nv_bfloat162*)(g_hh + o) = hh;
                    *(__nv_bfloat162*)(g_hl + o) = ll;
                } else {
                    int token = g_tok[e][r];
                    int slot  = g_slot[e][r];
                    float* dst = g_buf + ((size_t)slot * TOKENS + token) * DM + col;
                    *(float2*)dst = make_float2(v0, v1);
                }
            }
        }
    }
}

// ---------------- 4) combine ----------------
__global__ void combine_kernel(float* __restrict__ out) {
    int i = blockIdx.x * blockDim.x + threadIdx.x;
    const float4* b0 = (const float4*)g_buf;
    const float4* b1 = (const float4*)(g_buf + (size_t)TOKENS * DM);
    float4 u = b0[i], v = b1[i];
    ((float4*)out)[i] = make_float4(u.x + v.x, u.y + v.y, u.z + v.z, u.w + v.w);
}

// ---------------- host ----------------
extern "C" void kernel_launch(void* const* d_in, const int* in_sizes, int n_in,
                              void* d_out, int out_size) {
    const float* x  = (const float*)d_in[0];
    const float* Wg = (const float*)d_in[1];
    const float* bg = (const float*)d_in[2];
    const float* W1 = (const float*)d_in[3];
    const float* b1 = (const float*)d_in[4];
    const float* W2 = (const float*)d_in[5];
    const float* b2 = (const float*)d_in[6];
    float* out = (float*)d_out;

    cudaFuncSetAttribute(moe_gemm<DM, DF, true>,
                         cudaFuncAttributeMaxDynamicSharedMemorySize, SMEMB);
    cudaFuncSetAttribute(moe_gemm<DF, DM, false>,
                         cudaFuncAttributeMaxDynamicSharedMemorySize, SMEMB);

    zero_cnt_kernel<<<1, 32>>>();
    route_kernel<<<TOKENS / 8, 256>>>(x, Wg, bg);

    convert_x_kernel<<<TOKENS * DM / 4 / 256, 256>>>(x);
    convert_w_kernel<DM, DF, true><<<dim3(DF / 32, DM / 32, NE), dim3(32, 8)>>>(W1);
    convert_w_kernel<DF, DM, false><<<dim3(DM / 32, DF / 32, NE), dim3(32, 8)>>>(W2);

    // GEMM1: h = relu(gather(x) @ W1[e] + b1[e]) -> g_hh/g_hl
    moe_gemm<DM, DF, true><<<dim3(DF / 128, TOKENS / 128, NE), 256, SMEMB>>>(b1);
    // GEMM2: y = h @ W2[e] + b2[e] -> scatter into g_buf
    moe_gemm<DF, DM, false><<<dim3(DM / 128, TOKENS / 128, NE), 256, SMEMB>>>(b2);

    combine_kernel<<<(TOKENS * DM / 4) / 256, 256>>>(out);
}